// round 1
// baseline (speedup 1.0000x reference)
#include <cuda_runtime.h>
#include <math.h>

#define TKN 2048
#define BATCH 2
#define SEQ 1024
#define DIMX 1024
#define NH 16
#define NKV 4
#define HD 64
#define KVD (NKV*HD)   // 256
#define NE 8
#define FFX 4096

// ---------------- scratch (device globals; no runtime allocation) ----------------
__device__ float g_h1[TKN*DIMX];
__device__ float g_q [TKN*DIMX];
__device__ float g_k [TKN*KVD];
__device__ float g_v [TKN*KVD];
__device__ float g_attn[TKN*DIMX];
__device__ float g_x1[TKN*DIMX];
__device__ float g_h2[TKN*DIMX];
__device__ float g_hid[(size_t)NE*TKN*FFX];   // 256 MiB worst-case
__device__ float g_part[2*TKN*DIMX];          // slot0 rows [0,T), slot1 rows [T,2T)
__device__ int   g_tok [NE*TKN];
__device__ float g_gate[NE*TKN];
__device__ int   g_dest[NE*TKN];
__device__ int   g_ecnt[NE];
__device__ int   g_counts[NE];

// ---------------- small kernels ----------------
__global__ void zero_kernel() {
    int i = threadIdx.x;
    if (i < NE) { g_ecnt[i] = 0; g_counts[i] = 0; }
}

__global__ void ln_kernel(const float* __restrict__ x, const float* __restrict__ g,
                          const float* __restrict__ b, float* __restrict__ out) {
    int row = blockIdx.x;
    int tid = threadIdx.x;       // 256
    const float* xr = x + (size_t)row * DIMX;
    float v[4]; float s = 0.f;
    #pragma unroll
    for (int j = 0; j < 4; j++) { v[j] = xr[tid + 256*j]; s += v[j]; }
    __shared__ float red[8];
    #pragma unroll
    for (int o = 16; o > 0; o >>= 1) s += __shfl_xor_sync(0xffffffffu, s, o);
    if ((tid & 31) == 0) red[tid >> 5] = s;
    __syncthreads();
    float tot = red[0]+red[1]+red[2]+red[3]+red[4]+red[5]+red[6]+red[7];
    float mu = tot / DIMX;
    float sq = 0.f;
    #pragma unroll
    for (int j = 0; j < 4; j++) { float d = v[j]-mu; sq += d*d; }
    #pragma unroll
    for (int o = 16; o > 0; o >>= 1) sq += __shfl_xor_sync(0xffffffffu, sq, o);
    __syncthreads();
    if ((tid & 31) == 0) red[tid >> 5] = sq;
    __syncthreads();
    float vtot = red[0]+red[1]+red[2]+red[3]+red[4]+red[5]+red[6]+red[7];
    float rstd = rsqrtf(vtot / DIMX + 1e-5f);
    #pragma unroll
    for (int j = 0; j < 4; j++) {
        int d = tid + 256*j;
        out[(size_t)row*DIMX + d] = (v[j]-mu)*rstd*g[d] + b[d];
    }
}

// ---------------- generic 64x64x16 fp32 GEMM ----------------
// MODE 0: C = A@B (dense).  MODE 1: C = A@B + resid.
// MODE 2: MoE up:   z=expert; A rows gathered from g_h2 via g_tok; C = gelu(.) -> g_hid[e]
// MODE 3: MoE down: z=expert; A = g_hid[e]; C row i scattered to g_part[g_dest]*scale
template<int MODE>
__global__ void gemm_kernel(const float* __restrict__ A, const float* __restrict__ Bm,
                            float* __restrict__ C, const float* __restrict__ resid,
                            int M, int N, int K) {
    __shared__ float As[16][64];
    __shared__ float Bs[16][64];
    int e = blockIdx.z;
    if (MODE == 2) { M = g_ecnt[e]; A = g_h2;  Bm += (size_t)e*DIMX*FFX; C = g_hid + (size_t)e*TKN*FFX; }
    if (MODE == 3) { M = g_ecnt[e]; A = g_hid + (size_t)e*TKN*FFX; Bm += (size_t)e*FFX*DIMX; C = g_part; }
    int m0 = blockIdx.y * 64, n0 = blockIdx.x * 64;
    if (m0 >= M) return;
    int tid = threadIdx.x, tx = tid & 15, ty = tid >> 4;
    int ar = tid >> 2, ac = (tid & 3) << 2;       // A tile: 64 rows x 16 cols
    int br = tid >> 4, bc = (tid & 15) << 2;      // B tile: 16 rows x 64 cols
    float c[4][4] = {};
    for (int k0 = 0; k0 < K; k0 += 16) {
        float4 av = make_float4(0.f,0.f,0.f,0.f);
        int gr = m0 + ar;
        if (gr < M) {
            const float* ap = (MODE == 2) ? (A + (size_t)g_tok[e*TKN+gr]*K)
                                          : (A + (size_t)gr*K);
            av = *(const float4*)(ap + k0 + ac);
        }
        As[ac+0][ar]=av.x; As[ac+1][ar]=av.y; As[ac+2][ar]=av.z; As[ac+3][ar]=av.w;
        *(float4*)&Bs[br][bc] = *(const float4*)(Bm + (size_t)(k0+br)*N + n0 + bc);
        __syncthreads();
        #pragma unroll
        for (int kk = 0; kk < 16; kk++) {
            float4 a = *(float4*)&As[kk][ty << 2];
            float4 b = *(float4*)&Bs[kk][tx << 2];
            float aa[4] = {a.x,a.y,a.z,a.w}, bb[4] = {b.x,b.y,b.z,b.w};
            #pragma unroll
            for (int i = 0; i < 4; i++)
                #pragma unroll
                for (int j = 0; j < 4; j++) c[i][j] += aa[i]*bb[j];
        }
        __syncthreads();
    }
    #pragma unroll
    for (int i = 0; i < 4; i++) {
        int r = m0 + (ty << 2) + i;
        if (r >= M) break;
        int col = n0 + (tx << 2);
        if (MODE == 0) {
            float4 o = make_float4(c[i][0],c[i][1],c[i][2],c[i][3]);
            *(float4*)&C[(size_t)r*N + col] = o;
        } else if (MODE == 1) {
            float4 rr = *(const float4*)&resid[(size_t)r*N + col];
            float4 o = make_float4(c[i][0]+rr.x, c[i][1]+rr.y, c[i][2]+rr.z, c[i][3]+rr.w);
            *(float4*)&C[(size_t)r*N + col] = o;
        } else if (MODE == 2) {
            float4 o;
            float* po = &o.x;
            #pragma unroll
            for (int j = 0; j < 4; j++) {
                float xv = c[i][j];
                po[j] = 0.5f*xv*(1.0f + erff(xv*0.70710678118654752f));
            }
            *(float4*)&C[(size_t)r*N + col] = o;
        } else { // MODE 3
            int p = g_dest[e*TKN + r];
            float s = g_gate[e*TKN + r];
            float4 o = make_float4(s*c[i][0], s*c[i][1], s*c[i][2], s*c[i][3]);
            *(float4*)&C[(size_t)p*DIMX + col] = o;
        }
    }
}

// ---------------- RoPE (in place on g_q / g_k) ----------------
__global__ void rope_kernel() {
    int idx = blockIdx.x*blockDim.x + threadIdx.x;
    const int totq = TKN*NH*32;
    const int totk = TKN*NKV*32;
    float* arr; size_t base; int t, i;
    if (idx < totq) {
        arr = g_q; i = idx & 31; int rest = idx >> 5;
        int head = rest % NH; t = rest / NH;
        base = (size_t)t*DIMX + head*HD;
    } else {
        idx -= totq;
        if (idx >= totk) return;
        arr = g_k; i = idx & 31; int rest = idx >> 5;
        int head = rest % NKV; t = rest / NKV;
        base = (size_t)t*KVD + head*HD;
    }
    int pos = t % SEQ;
    float freq = expf(-(float)(2*i) * (9.210340371976184f / 64.0f)); // 10000^(-2i/64)
    float ang = (float)pos * freq;
    float cs = cosf(ang), sn = sinf(ang);
    float x1 = arr[base + i], x2 = arr[base + 32 + i];
    arr[base + i]      = x1*cs - x2*sn;
    arr[base + 32 + i] = x2*cs + x1*sn;
}

// ---------------- flash-style causal attention, 64-query tiles ----------------
__global__ void attn_kernel() {
    __shared__ float Qt[64][64];   // [d][r]
    __shared__ float KP[64][64];   // Kt[d][c], then Pt[c][r]
    __shared__ float Vs[64][64];   // [c][d]
    int qt = blockIdx.x, h = blockIdx.y, b = blockIdx.z;
    int hk = h >> 2;
    int tid = threadIdx.x, tx = tid & 15, ty = tid >> 4;
    int lr = tid >> 2, dbase = (tid & 3) << 4;
    {   // load Q tile transposed
        const float* qp = g_q + (size_t)(b*SEQ + qt*64 + lr)*DIMX + h*HD + dbase;
        #pragma unroll
        for (int jj = 0; jj < 4; jj++) {
            float4 v = *(const float4*)(qp + jj*4);
            Qt[dbase+jj*4+0][lr]=v.x; Qt[dbase+jj*4+1][lr]=v.y;
            Qt[dbase+jj*4+2][lr]=v.z; Qt[dbase+jj*4+3][lr]=v.w;
        }
    }
    float m[4], l[4], o[4][4] = {};
    #pragma unroll
    for (int i = 0; i < 4; i++) { m[i] = -3.0e38f; l[i] = 0.f; }

    for (int kt = 0; kt <= qt; kt++) {
        __syncthreads();  // previous iter's PV reads done; Q visible before first use
        {
            const float* kp = g_k + (size_t)(b*SEQ + kt*64 + lr)*KVD + hk*HD + dbase;
            const float* vp = g_v + (size_t)(b*SEQ + kt*64 + lr)*KVD + hk*HD + dbase;
            #pragma unroll
            for (int jj = 0; jj < 4; jj++) {
                float4 v = *(const float4*)(kp + jj*4);
                KP[dbase+jj*4+0][lr]=v.x; KP[dbase+jj*4+1][lr]=v.y;
                KP[dbase+jj*4+2][lr]=v.z; KP[dbase+jj*4+3][lr]=v.w;
                *(float4*)&Vs[lr][dbase+jj*4] = *(const float4*)(vp + jj*4);
            }
        }
        __syncthreads();
        float s[4][4] = {};
        #pragma unroll 8
        for (int d = 0; d < 64; d++) {
            float4 a = *(float4*)&Qt[d][ty << 2];
            float4 bv = *(float4*)&KP[d][tx << 2];
            float aa[4]={a.x,a.y,a.z,a.w}, bb[4]={bv.x,bv.y,bv.z,bv.w};
            #pragma unroll
            for (int i = 0; i < 4; i++)
                #pragma unroll
                for (int j = 0; j < 4; j++) s[i][j] += aa[i]*bb[j];
        }
        #pragma unroll
        for (int i = 0; i < 4; i++)
            #pragma unroll
            for (int j = 0; j < 4; j++) {
                s[i][j] *= 0.125f;
                if (kt == qt && ((tx<<2)+j) > ((ty<<2)+i)) s[i][j] = -1.0e30f;
            }
        // online softmax (row groups of 16 lanes)
        #pragma unroll
        for (int i = 0; i < 4; i++) {
            float mx = fmaxf(fmaxf(s[i][0], s[i][1]), fmaxf(s[i][2], s[i][3]));
            #pragma unroll
            for (int off = 8; off > 0; off >>= 1)
                mx = fmaxf(mx, __shfl_xor_sync(0xffffffffu, mx, off));
            float mn = fmaxf(m[i], mx);
            float corr = __expf(m[i] - mn);
            float rs = 0.f;
            #pragma unroll
            for (int j = 0; j < 4; j++) { s[i][j] = __expf(s[i][j] - mn); rs += s[i][j]; }
            #pragma unroll
            for (int off = 8; off > 0; off >>= 1)
                rs += __shfl_xor_sync(0xffffffffu, rs, off);
            l[i] = l[i]*corr + rs;
            #pragma unroll
            for (int j = 0; j < 4; j++) o[i][j] *= corr;
            m[i] = mn;
        }
        __syncthreads();   // done reading Kt
        #pragma unroll
        for (int i = 0; i < 4; i++)
            #pragma unroll
            for (int j = 0; j < 4; j++) KP[(tx<<2)+j][(ty<<2)+i] = s[i][j];  // Pt
        __syncthreads();
        #pragma unroll 8
        for (int cc = 0; cc < 64; cc++) {
            float4 a = *(float4*)&KP[cc][ty << 2];
            float4 bv = *(float4*)&Vs[cc][tx << 2];
            float aa[4]={a.x,a.y,a.z,a.w}, bb[4]={bv.x,bv.y,bv.z,bv.w};
            #pragma unroll
            for (int i = 0; i < 4; i++)
                #pragma unroll
                for (int j = 0; j < 4; j++) o[i][j] += aa[i]*bb[j];
        }
    }
    #pragma unroll
    for (int i = 0; i < 4; i++) {
        float inv = 1.0f / l[i];
        size_t rowb = (size_t)(b*SEQ + qt*64 + (ty<<2) + i)*DIMX + h*HD + (tx<<2);
        #pragma unroll
        for (int j = 0; j < 4; j++) g_attn[rowb + j] = o[i][j]*inv;
    }
}

// ---------------- router: top-2 + expert list build ----------------
__global__ void router_kernel(const float* __restrict__ wg) {
    int warp = (blockIdx.x*blockDim.x + threadIdx.x) >> 5;
    int lane = threadIdx.x & 31;
    if (warp >= TKN) return;
    int t = warp;
    float acc[NE] = {};
    const float* hr = g_h2 + (size_t)t*DIMX;
    for (int d = lane; d < DIMX; d += 32) {
        float hv = hr[d];
        const float* wr = wg + (size_t)d*NE;
        #pragma unroll
        for (int e = 0; e < NE; e++) acc[e] += hv * wr[e];
    }
    #pragma unroll
    for (int e = 0; e < NE; e++)
        #pragma unroll
        for (int off = 16; off > 0; off >>= 1)
            acc[e] += __shfl_xor_sync(0xffffffffu, acc[e], off);
    if (lane == 0) {
        int e0 = 0; float v0 = acc[0];
        #pragma unroll
        for (int e = 1; e < NE; e++) if (acc[e] > v0) { v0 = acc[e]; e0 = e; }
        int e1 = -1; float v1 = -3.4e38f;
        #pragma unroll
        for (int e = 0; e < NE; e++) if (e != e0 && acc[e] > v1) { v1 = acc[e]; e1 = e; }
        float ex = expf(v1 - v0);
        float den = 1.0f + ex;
        float gg0 = 1.0f/den, gg1 = ex/den;
        atomicAdd(&g_counts[e0], 1); atomicAdd(&g_counts[e1], 1);
        int p0 = atomicAdd(&g_ecnt[e0], 1);
        g_tok[e0*TKN+p0] = t; g_gate[e0*TKN+p0] = gg0; g_dest[e0*TKN+p0] = t;
        int p1 = atomicAdd(&g_ecnt[e1], 1);
        g_tok[e1*TKN+p1] = t; g_gate[e1*TKN+p1] = gg1; g_dest[e1*TKN+p1] = TKN + t;
    }
}

__global__ void combine_kernel(float* __restrict__ out) {
    int i = blockIdx.x*256 + threadIdx.x;
    out[i] = g_x1[i] + g_part[i] + g_part[TKN*DIMX + i];
}

__global__ void lb_kernel(float* __restrict__ out, int out_size) {
    if (threadIdx.x == 0) {
        float tot = 0.f;
        for (int e = 0; e < NE; e++) tot += (float)g_counts[e];
        float loss = 0.f;
        for (int e = 0; e < NE; e++) {
            float cn = (float)g_counts[e]/tot - 1.0f/NE;
            loss += cn*cn;
        }
        out[out_size - 1] = loss / NE;
    }
}

// ---------------- launch ----------------
extern "C" void kernel_launch(void* const* d_in, const int* in_sizes, int n_in,
                              void* d_out, int out_size) {
    const float* x    = (const float*)d_in[0];
    const float* wq   = (const float*)d_in[1];
    const float* wk   = (const float*)d_in[2];
    const float* wv   = (const float*)d_in[3];
    const float* wo   = (const float*)d_in[4];
    const float* wg   = (const float*)d_in[5];
    const float* w1   = (const float*)d_in[6];
    const float* w2   = (const float*)d_in[7];
    const float* ln1g = (const float*)d_in[8];
    const float* ln1b = (const float*)d_in[9];
    const float* ln2g = (const float*)d_in[10];
    const float* ln2b = (const float*)d_in[11];
    float* out = (float*)d_out;

    float *p_h1, *p_q, *p_k, *p_v, *p_attn, *p_x1, *p_h2;
    cudaGetSymbolAddress((void**)&p_h1,  g_h1);
    cudaGetSymbolAddress((void**)&p_q,   g_q);
    cudaGetSymbolAddress((void**)&p_k,   g_k);
    cudaGetSymbolAddress((void**)&p_v,   g_v);
    cudaGetSymbolAddress((void**)&p_attn,g_attn);
    cudaGetSymbolAddress((void**)&p_x1,  g_x1);
    cudaGetSymbolAddress((void**)&p_h2,  g_h2);

    zero_kernel<<<1, 32>>>();
    ln_kernel<<<TKN, 256>>>(x, ln1g, ln1b, p_h1);

    gemm_kernel<0><<<dim3(DIMX/64, TKN/64, 1), 256>>>(p_h1, wq, p_q, nullptr, TKN, DIMX, DIMX);
    gemm_kernel<0><<<dim3(KVD/64,  TKN/64, 1), 256>>>(p_h1, wk, p_k, nullptr, TKN, KVD, DIMX);
    gemm_kernel<0><<<dim3(KVD/64,  TKN/64, 1), 256>>>(p_h1, wv, p_v, nullptr, TKN, KVD, DIMX);

    rope_kernel<<<(TKN*(NH+NKV)*32)/256, 256>>>();
    attn_kernel<<<dim3(SEQ/64, NH, BATCH), 256>>>();

    gemm_kernel<1><<<dim3(DIMX/64, TKN/64, 1), 256>>>(p_attn, wo, p_x1, x, TKN, DIMX, DIMX);
    ln_kernel<<<TKN, 256>>>(p_x1, ln2g, ln2b, p_h2);

    router_kernel<<<TKN/8, 256>>>(wg);

    gemm_kernel<2><<<dim3(FFX/64,  TKN/64, NE), 256>>>(nullptr, w1, nullptr, nullptr, TKN, FFX, DIMX);
    gemm_kernel<3><<<dim3(DIMX/64, TKN/64, NE), 256>>>(nullptr, w2, nullptr, nullptr, TKN, DIMX, FFX);

    combine_kernel<<<(TKN*DIMX)/256, 256>>>(out);
    lb_kernel<<<1, 32>>>(out, out_size);
}

// round 2
// speedup vs baseline: 2.7542x; 2.7542x over previous
#include <cuda_runtime.h>
#include <math.h>

#define TKN 2048
#define BATCH 2
#define SEQ 1024
#define DIMX 1024
#define NH 16
#define NKV 4
#define HD 64
#define KVD (NKV*HD)   // 256
#define NE 8
#define FFX 4096

// ---------------- scratch (device globals; no runtime allocation) ----------------
__device__ float g_h1[TKN*DIMX];
__device__ float g_q [TKN*DIMX];
__device__ float g_k [TKN*KVD];
__device__ float g_v [TKN*KVD];
__device__ float g_attn[TKN*DIMX];
__device__ float g_x1[TKN*DIMX];
__device__ float g_h2[TKN*DIMX];
__device__ float g_hid[(size_t)NE*TKN*FFX];
__device__ float g_part[2*TKN*DIMX];
__device__ int   g_tok [NE*TKN];
__device__ float g_gate[NE*TKN];
__device__ int   g_dest[NE*TKN];
__device__ int   g_ecnt[NE];
__device__ int   g_counts[NE];

// ---------------- small kernels ----------------
__global__ void zero_kernel() {
    int i = threadIdx.x;
    if (i < NE) { g_ecnt[i] = 0; g_counts[i] = 0; }
}

__global__ void ln_kernel(const float* __restrict__ x, const float* __restrict__ g,
                          const float* __restrict__ b, float* __restrict__ out) {
    int row = blockIdx.x;
    int tid = threadIdx.x;       // 256
    const float* xr = x + (size_t)row * DIMX;
    float v[4]; float s = 0.f;
    #pragma unroll
    for (int j = 0; j < 4; j++) { v[j] = xr[tid + 256*j]; s += v[j]; }
    __shared__ float red[8];
    #pragma unroll
    for (int o = 16; o > 0; o >>= 1) s += __shfl_xor_sync(0xffffffffu, s, o);
    if ((tid & 31) == 0) red[tid >> 5] = s;
    __syncthreads();
    float tot = red[0]+red[1]+red[2]+red[3]+red[4]+red[5]+red[6]+red[7];
    float mu = tot / DIMX;
    float sq = 0.f;
    #pragma unroll
    for (int j = 0; j < 4; j++) { float d = v[j]-mu; sq += d*d; }
    #pragma unroll
    for (int o = 16; o > 0; o >>= 1) sq += __shfl_xor_sync(0xffffffffu, sq, o);
    __syncthreads();
    if ((tid & 31) == 0) red[tid >> 5] = sq;
    __syncthreads();
    float vtot = red[0]+red[1]+red[2]+red[3]+red[4]+red[5]+red[6]+red[7];
    float rstd = rsqrtf(vtot / DIMX + 1e-5f);
    #pragma unroll
    for (int j = 0; j < 4; j++) {
        int d = tid + 256*j;
        out[(size_t)row*DIMX + d] = (v[j]-mu)*rstd*g[d] + b[d];
    }
}

// ---------------- tf32 tensor-core GEMM: 128x128x16 tiles, 8 warps ----------------
// MODE 0: C = A@B.  MODE 1: C = A@B + resid.
// MODE 2: MoE up (gather rows via g_tok, GELU epilogue -> g_hid[e])
// MODE 3: MoE down (A = g_hid[e], scatter rows via g_dest, scale by g_gate -> g_part)
#define BM 128
#define BN 128
#define BKK 16

__device__ __forceinline__ unsigned f2tf(float f) {
    unsigned u; asm("cvt.rna.tf32.f32 %0, %1;" : "=r"(u) : "f"(f)); return u;
}

template<int MODE>
__global__ __launch_bounds__(256, 2)
void mma_gemm(const float* __restrict__ A, const float* __restrict__ Bm,
              float* __restrict__ C, const float* __restrict__ resid,
              int M, int N, int K) {
    __shared__ float As[2][BM][20];    // row-major [m][k], stride 20 -> conflict-free frags
    __shared__ float Bs[2][BKK][136];  // [k][n], stride 136 -> conflict-free frags
    int e = blockIdx.z;
    if (MODE == 2) { M = g_ecnt[e]; A = g_h2;  Bm += (size_t)e*DIMX*FFX; C = g_hid + (size_t)e*TKN*FFX; }
    if (MODE == 3) { M = g_ecnt[e]; A = g_hid + (size_t)e*TKN*FFX; Bm += (size_t)e*FFX*DIMX; C = g_part; }
    int m0 = blockIdx.y * BM, n0 = blockIdx.x * BN;
    if (m0 >= M) return;
    int tid = threadIdx.x;
    int warp = tid >> 5, lane = tid & 31;
    int wm = warp >> 2, wn = warp & 3;       // warp tile: 64 x 32
    int g  = lane >> 2, tg = lane & 3;

    // per-thread load slots (fixed across K loop)
    const float* aSrc[2]; int aSz[2]; unsigned aDst[2];
    #pragma unroll
    for (int p = 0; p < 2; p++) {
        int v = tid + p*256;
        int ar = v >> 2, ac = (v & 3) << 2;
        int rg = m0 + ar;
        bool valid = rg < M;
        const float* ptr;
        if (MODE == 2) {
            int t = valid ? g_tok[e*TKN + rg] : 0;
            ptr = A + (size_t)t*K + ac;
        } else {
            ptr = A + (size_t)(valid ? rg : 0)*K + ac;
        }
        aSrc[p] = ptr; aSz[p] = valid ? 16 : 0;
        aDst[p] = (unsigned)__cvta_generic_to_shared(&As[0][ar][ac]);
    }
    const float* bSrc[2]; unsigned bDst[2];
    #pragma unroll
    for (int p = 0; p < 2; p++) {
        int v = tid + p*256;
        int br = v >> 5, bc = (v & 31) << 2;
        bSrc[p] = Bm + (size_t)br*N + n0 + bc;
        bDst[p] = (unsigned)__cvta_generic_to_shared(&Bs[0][br][bc]);
    }
    const unsigned aBufSz = BM*20*4, bBufSz = BKK*136*4;

    auto load_tiles = [&](int buf, int k0) {
        #pragma unroll
        for (int p = 0; p < 2; p++)
            asm volatile("cp.async.cg.shared.global [%0], [%1], 16, %2;"
                :: "r"(aDst[p] + buf*aBufSz), "l"(aSrc[p] + k0), "r"(aSz[p]));
        #pragma unroll
        for (int p = 0; p < 2; p++)
            asm volatile("cp.async.cg.shared.global [%0], [%1], 16;"
                :: "r"(bDst[p] + buf*bBufSz), "l"(bSrc[p] + (size_t)k0*N));
        asm volatile("cp.async.commit_group;");
    };

    float c[4][4][4] = {};
    int nk = K / BKK;
    load_tiles(0, 0);
    int buf = 0;
    for (int kt = 0; kt < nk; kt++) {
        if (kt + 1 < nk) {
            load_tiles(buf ^ 1, (kt + 1)*BKK);
            asm volatile("cp.async.wait_group 1;");
        } else {
            asm volatile("cp.async.wait_group 0;");
        }
        __syncthreads();
        #pragma unroll
        for (int ks = 0; ks < 2; ks++) {
            int kk = ks*8;
            unsigned af[4][4], bf[4][2];
            #pragma unroll
            for (int i = 0; i < 4; i++) {
                int r = wm*64 + i*16 + g;
                af[i][0] = f2tf(As[buf][r    ][kk + tg    ]);
                af[i][1] = f2tf(As[buf][r + 8][kk + tg    ]);
                af[i][2] = f2tf(As[buf][r    ][kk + tg + 4]);
                af[i][3] = f2tf(As[buf][r + 8][kk + tg + 4]);
            }
            #pragma unroll
            for (int j = 0; j < 4; j++) {
                int cc = wn*32 + j*8 + g;
                bf[j][0] = f2tf(Bs[buf][kk + tg    ][cc]);
                bf[j][1] = f2tf(Bs[buf][kk + tg + 4][cc]);
            }
            #pragma unroll
            for (int i = 0; i < 4; i++)
                #pragma unroll
                for (int j = 0; j < 4; j++)
                    asm volatile(
                        "mma.sync.aligned.m16n8k8.row.col.f32.tf32.tf32.f32 "
                        "{%0,%1,%2,%3},{%4,%5,%6,%7},{%8,%9},{%0,%1,%2,%3};"
                        : "+f"(c[i][j][0]), "+f"(c[i][j][1]), "+f"(c[i][j][2]), "+f"(c[i][j][3])
                        : "r"(af[i][0]), "r"(af[i][1]), "r"(af[i][2]), "r"(af[i][3]),
                          "r"(bf[j][0]), "r"(bf[j][1]));
        }
        __syncthreads();
        buf ^= 1;
    }

    // epilogue
    #pragma unroll
    for (int i = 0; i < 4; i++) {
        #pragma unroll
        for (int half = 0; half < 2; half++) {
            int r = m0 + wm*64 + i*16 + g + half*8;
            if (MODE >= 2 && r >= M) continue;
            #pragma unroll
            for (int j = 0; j < 4; j++) {
                float v0 = c[i][j][half*2 + 0];
                float v1 = c[i][j][half*2 + 1];
                int col = n0 + wn*32 + j*8 + 2*tg;
                if (MODE == 0) {
                    float2 o = make_float2(v0, v1);
                    *(float2*)&C[(size_t)r*N + col] = o;
                } else if (MODE == 1) {
                    float2 rr = *(const float2*)&resid[(size_t)r*N + col];
                    float2 o = make_float2(v0 + rr.x, v1 + rr.y);
                    *(float2*)&C[(size_t)r*N + col] = o;
                } else if (MODE == 2) {
                    float2 o;
                    o.x = 0.5f*v0*(1.0f + erff(v0*0.70710678118654752f));
                    o.y = 0.5f*v1*(1.0f + erff(v1*0.70710678118654752f));
                    *(float2*)&C[(size_t)r*N + col] = o;
                } else { // MODE 3
                    int p = g_dest[e*TKN + r];
                    float s = g_gate[e*TKN + r];
                    float2 o = make_float2(s*v0, s*v1);
                    *(float2*)&g_part[(size_t)p*DIMX + col] = o;
                }
            }
        }
    }
}

// ---------------- RoPE (in place on g_q / g_k) ----------------
__global__ void rope_kernel() {
    int idx = blockIdx.x*blockDim.x + threadIdx.x;
    const int totq = TKN*NH*32;
    const int totk = TKN*NKV*32;
    float* arr; size_t base; int t, i;
    if (idx < totq) {
        arr = g_q; i = idx & 31; int rest = idx >> 5;
        int head = rest % NH; t = rest / NH;
        base = (size_t)t*DIMX + head*HD;
    } else {
        idx -= totq;
        if (idx >= totk) return;
        arr = g_k; i = idx & 31; int rest = idx >> 5;
        int head = rest % NKV; t = rest / NKV;
        base = (size_t)t*KVD + head*HD;
    }
    int pos = t % SEQ;
    float freq = expf(-(float)(2*i) * (9.210340371976184f / 64.0f));
    float ang = (float)pos * freq;
    float cs = cosf(ang), sn = sinf(ang);
    float x1 = arr[base + i], x2 = arr[base + 32 + i];
    arr[base + i]      = x1*cs - x2*sn;
    arr[base + 32 + i] = x2*cs + x1*sn;
}

// ---------------- flash-style causal attention, 64-query tiles ----------------
__global__ void attn_kernel() {
    __shared__ float Qt[64][64];
    __shared__ float KP[64][64];
    __shared__ float Vs[64][64];
    int qt = blockIdx.x, h = blockIdx.y, b = blockIdx.z;
    int hk = h >> 2;
    int tid = threadIdx.x, tx = tid & 15, ty = tid >> 4;
    int lr = tid >> 2, dbase = (tid & 3) << 4;
    {
        const float* qp = g_q + (size_t)(b*SEQ + qt*64 + lr)*DIMX + h*HD + dbase;
        #pragma unroll
        for (int jj = 0; jj < 4; jj++) {
            float4 v = *(const float4*)(qp + jj*4);
            Qt[dbase+jj*4+0][lr]=v.x; Qt[dbase+jj*4+1][lr]=v.y;
            Qt[dbase+jj*4+2][lr]=v.z; Qt[dbase+jj*4+3][lr]=v.w;
        }
    }
    float m[4], l[4], o[4][4] = {};
    #pragma unroll
    for (int i = 0; i < 4; i++) { m[i] = -3.0e38f; l[i] = 0.f; }

    for (int kt = 0; kt <= qt; kt++) {
        __syncthreads();
        {
            const float* kp = g_k + (size_t)(b*SEQ + kt*64 + lr)*KVD + hk*HD + dbase;
            const float* vp = g_v + (size_t)(b*SEQ + kt*64 + lr)*KVD + hk*HD + dbase;
            #pragma unroll
            for (int jj = 0; jj < 4; jj++) {
                float4 v = *(const float4*)(kp + jj*4);
                KP[dbase+jj*4+0][lr]=v.x; KP[dbase+jj*4+1][lr]=v.y;
                KP[dbase+jj*4+2][lr]=v.z; KP[dbase+jj*4+3][lr]=v.w;
                *(float4*)&Vs[lr][dbase+jj*4] = *(const float4*)(vp + jj*4);
            }
        }
        __syncthreads();
        float s[4][4] = {};
        #pragma unroll 8
        for (int d = 0; d < 64; d++) {
            float4 a = *(float4*)&Qt[d][ty << 2];
            float4 bv = *(float4*)&KP[d][tx << 2];
            float aa[4]={a.x,a.y,a.z,a.w}, bb[4]={bv.x,bv.y,bv.z,bv.w};
            #pragma unroll
            for (int i = 0; i < 4; i++)
                #pragma unroll
                for (int j = 0; j < 4; j++) s[i][j] += aa[i]*bb[j];
        }
        #pragma unroll
        for (int i = 0; i < 4; i++)
            #pragma unroll
            for (int j = 0; j < 4; j++) {
                s[i][j] *= 0.125f;
                if (kt == qt && ((tx<<2)+j) > ((ty<<2)+i)) s[i][j] = -1.0e30f;
            }
        #pragma unroll
        for (int i = 0; i < 4; i++) {
            float mx = fmaxf(fmaxf(s[i][0], s[i][1]), fmaxf(s[i][2], s[i][3]));
            #pragma unroll
            for (int off = 8; off > 0; off >>= 1)
                mx = fmaxf(mx, __shfl_xor_sync(0xffffffffu, mx, off));
            float mn = fmaxf(m[i], mx);
            float corr = __expf(m[i] - mn);
            float rs = 0.f;
            #pragma unroll
            for (int j = 0; j < 4; j++) { s[i][j] = __expf(s[i][j] - mn); rs += s[i][j]; }
            #pragma unroll
            for (int off = 8; off > 0; off >>= 1)
                rs += __shfl_xor_sync(0xffffffffu, rs, off);
            l[i] = l[i]*corr + rs;
            #pragma unroll
            for (int j = 0; j < 4; j++) o[i][j] *= corr;
            m[i] = mn;
        }
        __syncthreads();
        #pragma unroll
        for (int i = 0; i < 4; i++)
            #pragma unroll
            for (int j = 0; j < 4; j++) KP[(tx<<2)+j][(ty<<2)+i] = s[i][j];
        __syncthreads();
        #pragma unroll 8
        for (int cc = 0; cc < 64; cc++) {
            float4 a = *(float4*)&KP[cc][ty << 2];
            float4 bv = *(float4*)&Vs[cc][tx << 2];
            float aa[4]={a.x,a.y,a.z,a.w}, bb[4]={bv.x,bv.y,bv.z,bv.w};
            #pragma unroll
            for (int i = 0; i < 4; i++)
                #pragma unroll
                for (int j = 0; j < 4; j++) o[i][j] += aa[i]*bb[j];
        }
    }
    #pragma unroll
    for (int i = 0; i < 4; i++) {
        float inv = 1.0f / l[i];
        size_t rowb = (size_t)(b*SEQ + qt*64 + (ty<<2) + i)*DIMX + h*HD + (tx<<2);
        #pragma unroll
        for (int j = 0; j < 4; j++) g_attn[rowb + j] = o[i][j]*inv;
    }
}

// ---------------- router: top-2 + expert list build ----------------
__global__ void router_kernel(const float* __restrict__ wg) {
    int warp = (blockIdx.x*blockDim.x + threadIdx.x) >> 5;
    int lane = threadIdx.x & 31;
    if (warp >= TKN) return;
    int t = warp;
    float acc[NE] = {};
    const float* hr = g_h2 + (size_t)t*DIMX;
    for (int d = lane; d < DIMX; d += 32) {
        float hv = hr[d];
        const float* wr = wg + (size_t)d*NE;
        #pragma unroll
        for (int e = 0; e < NE; e++) acc[e] += hv * wr[e];
    }
    #pragma unroll
    for (int e = 0; e < NE; e++)
        #pragma unroll
        for (int off = 16; off > 0; off >>= 1)
            acc[e] += __shfl_xor_sync(0xffffffffu, acc[e], off);
    if (lane == 0) {
        int e0 = 0; float v0 = acc[0];
        #pragma unroll
        for (int e = 1; e < NE; e++) if (acc[e] > v0) { v0 = acc[e]; e0 = e; }
        int e1 = -1; float v1 = -3.4e38f;
        #pragma unroll
        for (int e = 0; e < NE; e++) if (e != e0 && acc[e] > v1) { v1 = acc[e]; e1 = e; }
        float ex = expf(v1 - v0);
        float den = 1.0f + ex;
        float gg0 = 1.0f/den, gg1 = ex/den;
        atomicAdd(&g_counts[e0], 1); atomicAdd(&g_counts[e1], 1);
        int p0 = atomicAdd(&g_ecnt[e0], 1);
        g_tok[e0*TKN+p0] = t; g_gate[e0*TKN+p0] = gg0; g_dest[e0*TKN+p0] = t;
        int p1 = atomicAdd(&g_ecnt[e1], 1);
        g_tok[e1*TKN+p1] = t; g_gate[e1*TKN+p1] = gg1; g_dest[e1*TKN+p1] = TKN + t;
    }
}

__global__ void combine_kernel(float* __restrict__ out) {
    int i = blockIdx.x*256 + threadIdx.x;
    out[i] = g_x1[i] + g_part[i] + g_part[TKN*DIMX + i];
}

__global__ void lb_kernel(float* __restrict__ out, int out_size) {
    if (threadIdx.x == 0) {
        float tot = 0.f;
        for (int e = 0; e < NE; e++) tot += (float)g_counts[e];
        float loss = 0.f;
        for (int e = 0; e < NE; e++) {
            float cn = (float)g_counts[e]/tot - 1.0f/NE;
            loss += cn*cn;
        }
        out[out_size - 1] = loss / NE;
    }
}

// ---------------- launch ----------------
extern "C" void kernel_launch(void* const* d_in, const int* in_sizes, int n_in,
                              void* d_out, int out_size) {
    const float* x    = (const float*)d_in[0];
    const float* wq   = (const float*)d_in[1];
    const float* wk   = (const float*)d_in[2];
    const float* wv   = (const float*)d_in[3];
    const float* wo   = (const float*)d_in[4];
    const float* wg   = (const float*)d_in[5];
    const float* w1   = (const float*)d_in[6];
    const float* w2   = (const float*)d_in[7];
    const float* ln1g = (const float*)d_in[8];
    const float* ln1b = (const float*)d_in[9];
    const float* ln2g = (const float*)d_in[10];
    const float* ln2b = (const float*)d_in[11];
    float* out = (float*)d_out;

    float *p_h1, *p_q, *p_k, *p_v, *p_attn, *p_x1, *p_h2;
    cudaGetSymbolAddress((void**)&p_h1,  g_h1);
    cudaGetSymbolAddress((void**)&p_q,   g_q);
    cudaGetSymbolAddress((void**)&p_k,   g_k);
    cudaGetSymbolAddress((void**)&p_v,   g_v);
    cudaGetSymbolAddress((void**)&p_attn,g_attn);
    cudaGetSymbolAddress((void**)&p_x1,  g_x1);
    cudaGetSymbolAddress((void**)&p_h2,  g_h2);

    zero_kernel<<<1, 32>>>();
    ln_kernel<<<TKN, 256>>>(x, ln1g, ln1b, p_h1);

    mma_gemm<0><<<dim3(DIMX/BN, TKN/BM, 1), 256>>>(p_h1, wq, p_q, nullptr, TKN, DIMX, DIMX);
    mma_gemm<0><<<dim3(KVD/BN,  TKN/BM, 1), 256>>>(p_h1, wk, p_k, nullptr, TKN, KVD, DIMX);
    mma_gemm<0><<<dim3(KVD/BN,  TKN/BM, 1), 256>>>(p_h1, wv, p_v, nullptr, TKN, KVD, DIMX);

    rope_kernel<<<(TKN*(NH+NKV)*32)/256, 256>>>();
    attn_kernel<<<dim3(SEQ/64, NH, BATCH), 256>>>();

    mma_gemm<1><<<dim3(DIMX/BN, TKN/BM, 1), 256>>>(p_attn, wo, p_x1, x, TKN, DIMX, DIMX);
    ln_kernel<<<TKN, 256>>>(p_x1, ln2g, ln2b, p_h2);

    router_kernel<<<TKN/8, 256>>>(wg);

    mma_gemm<2><<<dim3(FFX/BN,  TKN/BM, NE), 256>>>(nullptr, w1, nullptr, nullptr, TKN, FFX, DIMX);
    mma_gemm<3><<<dim3(DIMX/BN, TKN/BM, NE), 256>>>(nullptr, w2, nullptr, nullptr, TKN, DIMX, FFX);

    combine_kernel<<<(TKN*DIMX)/256, 256>>>(out);
    lb_kernel<<<1, 32>>>(out, out_size);
}

// round 3
// speedup vs baseline: 3.8553x; 1.3998x over previous
#include <cuda_runtime.h>
#include <math.h>

#define TKN 2048
#define BATCH 2
#define SEQ 1024
#define DIMX 1024
#define NH 16
#define NKV 4
#define HD 64
#define KVD (NKV*HD)   // 256
#define NE 8
#define FFX 4096

// ---------------- scratch ----------------
__device__ float g_h1[TKN*DIMX];
__device__ float g_q [TKN*DIMX];
__device__ float g_k [TKN*KVD];
__device__ float g_v [TKN*KVD];
__device__ float g_attn[TKN*DIMX];
__device__ float g_x1[TKN*DIMX];
__device__ float g_h2[TKN*DIMX];
__device__ float g_hid[(size_t)NE*TKN*FFX];
__device__ float g_part[2*TKN*DIMX];
__device__ int   g_tok [NE*TKN];
__device__ float g_gate[NE*TKN];
__device__ int   g_dest[NE*TKN];
__device__ int   g_ecnt[NE];
__device__ int   g_counts[NE];

__global__ void zero_kernel() {
    int i = threadIdx.x;
    if (i < NE) { g_ecnt[i] = 0; g_counts[i] = 0; }
}

__global__ void ln_kernel(const float* __restrict__ x, const float* __restrict__ g,
                          const float* __restrict__ b, float* __restrict__ out) {
    int row = blockIdx.x;
    int tid = threadIdx.x;
    const float* xr = x + (size_t)row * DIMX;
    float v[4]; float s = 0.f;
    #pragma unroll
    for (int j = 0; j < 4; j++) { v[j] = xr[tid + 256*j]; s += v[j]; }
    __shared__ float red[8];
    #pragma unroll
    for (int o = 16; o > 0; o >>= 1) s += __shfl_xor_sync(0xffffffffu, s, o);
    if ((tid & 31) == 0) red[tid >> 5] = s;
    __syncthreads();
    float tot = red[0]+red[1]+red[2]+red[3]+red[4]+red[5]+red[6]+red[7];
    float mu = tot / DIMX;
    float sq = 0.f;
    #pragma unroll
    for (int j = 0; j < 4; j++) { float d = v[j]-mu; sq += d*d; }
    #pragma unroll
    for (int o = 16; o > 0; o >>= 1) sq += __shfl_xor_sync(0xffffffffu, sq, o);
    __syncthreads();
    if ((tid & 31) == 0) red[tid >> 5] = sq;
    __syncthreads();
    float vtot = red[0]+red[1]+red[2]+red[3]+red[4]+red[5]+red[6]+red[7];
    float rstd = rsqrtf(vtot / DIMX + 1e-5f);
    #pragma unroll
    for (int j = 0; j < 4; j++) {
        int d = tid + 256*j;
        out[(size_t)row*DIMX + d] = (v[j]-mu)*rstd*g[d] + b[d];
    }
}

// ---------------- tf32 tensor-core GEMM ----------------
// MODE 0: C=A@B  MODE 1: +resid  MODE 2: MoE up (gather+GELU)
// MODE 3: MoE down (scatter*gate)  MODE 4: fused QKV (B/C selected per block)
#define BM 128
#define BN 128
#define BKK 16

#define MMA_TF32(C4, A0,A1,A2,A3, B0,B1) \
    asm volatile("mma.sync.aligned.m16n8k8.row.col.f32.tf32.tf32.f32 " \
        "{%0,%1,%2,%3},{%4,%5,%6,%7},{%8,%9},{%0,%1,%2,%3};" \
        : "+f"(C4[0]), "+f"(C4[1]), "+f"(C4[2]), "+f"(C4[3]) \
        : "r"(A0), "r"(A1), "r"(A2), "r"(A3), "r"(B0), "r"(B1))

template<int MODE>
__global__ __launch_bounds__(256, 2)
void mma_gemm(const float* __restrict__ A, const float* __restrict__ Bm,
              float* __restrict__ C, const float* __restrict__ resid,
              const float* __restrict__ wkp, const float* __restrict__ wvp,
              int M, int N, int K) {
    __shared__ float As[2][BM][20];
    __shared__ float Bs[2][BKK][136];
    int e = blockIdx.z;
    int ldB = N, ldC = N;
    int n0 = blockIdx.x * BN, cbase = n0;
    if (MODE == 2) { M = g_ecnt[e]; A = g_h2;  Bm += (size_t)e*DIMX*FFX; C = g_hid + (size_t)e*TKN*FFX; }
    if (MODE == 3) { M = g_ecnt[e]; A = g_hid + (size_t)e*TKN*FFX; Bm += (size_t)e*FFX*DIMX; C = g_part; ldC = DIMX; }
    if (MODE == 4) {
        if (n0 < DIMX)            {                    ldB = DIMX; C = g_q; ldC = DIMX; cbase = n0; }
        else if (n0 < DIMX + KVD) { Bm = wkp;          ldB = KVD;  C = g_k; ldC = KVD;  cbase = n0 - DIMX; }
        else                      { Bm = wvp;          ldB = KVD;  C = g_v; ldC = KVD;  cbase = n0 - DIMX - KVD; }
    }
    int m0 = blockIdx.y * BM;
    if (m0 >= M) return;
    int tid = threadIdx.x;
    int warp = tid >> 5, lane = tid & 31;
    int wm = warp >> 2, wn = warp & 3;
    int g  = lane >> 2, tg = lane & 3;

    const float* aSrc[2]; int aSz[2]; unsigned aDst[2];
    #pragma unroll
    for (int p = 0; p < 2; p++) {
        int v = tid + p*256;
        int ar = v >> 2, ac = (v & 3) << 2;
        int rg = m0 + ar;
        bool valid = rg < M;
        const float* ptr;
        if (MODE == 2) {
            int t = valid ? g_tok[e*TKN + rg] : 0;
            ptr = A + (size_t)t*K + ac;
        } else {
            ptr = A + (size_t)(valid ? rg : 0)*K + ac;
        }
        aSrc[p] = ptr; aSz[p] = valid ? 16 : 0;
        aDst[p] = (unsigned)__cvta_generic_to_shared(&As[0][ar][ac]);
    }
    const float* bSrc[2]; unsigned bDst[2];
    #pragma unroll
    for (int p = 0; p < 2; p++) {
        int v = tid + p*256;
        int br = v >> 5, bc = (v & 31) << 2;
        bSrc[p] = Bm + (size_t)br*ldB + cbase + bc;
        bDst[p] = (unsigned)__cvta_generic_to_shared(&Bs[0][br][bc]);
    }
    const unsigned aBufSz = BM*20*4, bBufSz = BKK*136*4;

    auto load_tiles = [&](int buf, int k0) {
        #pragma unroll
        for (int p = 0; p < 2; p++)
            asm volatile("cp.async.cg.shared.global [%0], [%1], 16, %2;"
                :: "r"(aDst[p] + buf*aBufSz), "l"(aSrc[p] + k0), "r"(aSz[p]));
        #pragma unroll
        for (int p = 0; p < 2; p++)
            asm volatile("cp.async.cg.shared.global [%0], [%1], 16;"
                :: "r"(bDst[p] + buf*bBufSz), "l"(bSrc[p] + (size_t)k0*ldB));
        asm volatile("cp.async.commit_group;");
    };

    float c[4][4][4] = {};
    int nk = K / BKK;
    load_tiles(0, 0);
    int buf = 0;
    for (int kt = 0; kt < nk; kt++) {
        if (kt + 1 < nk) {
            load_tiles(buf ^ 1, (kt + 1)*BKK);
            asm volatile("cp.async.wait_group 1;");
        } else {
            asm volatile("cp.async.wait_group 0;");
        }
        __syncthreads();
        #pragma unroll
        for (int ks = 0; ks < 2; ks++) {
            int kk = ks*8;
            unsigned af[4][4], bf[4][2];
            #pragma unroll
            for (int i = 0; i < 4; i++) {
                int r = wm*64 + i*16 + g;
                af[i][0] = __float_as_uint(As[buf][r    ][kk + tg    ]);
                af[i][1] = __float_as_uint(As[buf][r + 8][kk + tg    ]);
                af[i][2] = __float_as_uint(As[buf][r    ][kk + tg + 4]);
                af[i][3] = __float_as_uint(As[buf][r + 8][kk + tg + 4]);
            }
            #pragma unroll
            for (int j = 0; j < 4; j++) {
                int cc = wn*32 + j*8 + g;
                bf[j][0] = __float_as_uint(Bs[buf][kk + tg    ][cc]);
                bf[j][1] = __float_as_uint(Bs[buf][kk + tg + 4][cc]);
            }
            #pragma unroll
            for (int i = 0; i < 4; i++)
                #pragma unroll
                for (int j = 0; j < 4; j++)
                    MMA_TF32(c[i][j], af[i][0], af[i][1], af[i][2], af[i][3],
                             bf[j][0], bf[j][1]);
        }
        __syncthreads();
        buf ^= 1;
    }

    #pragma unroll
    for (int i = 0; i < 4; i++) {
        #pragma unroll
        for (int half = 0; half < 2; half++) {
            int r = m0 + wm*64 + i*16 + g + half*8;
            if (MODE >= 2 && MODE != 4 && r >= M) continue;
            #pragma unroll
            for (int j = 0; j < 4; j++) {
                float v0 = c[i][j][half*2 + 0];
                float v1 = c[i][j][half*2 + 1];
                int col = cbase + wn*32 + j*8 + 2*tg;
                if (MODE == 0 || MODE == 4) {
                    *(float2*)&C[(size_t)r*ldC + col] = make_float2(v0, v1);
                } else if (MODE == 1) {
                    float2 rr = *(const float2*)&resid[(size_t)r*ldC + col];
                    *(float2*)&C[(size_t)r*ldC + col] = make_float2(v0+rr.x, v1+rr.y);
                } else if (MODE == 2) {
                    float2 o;
                    o.x = 0.5f*v0*(1.0f + erff(v0*0.70710678118654752f));
                    o.y = 0.5f*v1*(1.0f + erff(v1*0.70710678118654752f));
                    *(float2*)&C[(size_t)r*ldC + col] = o;
                } else {
                    int p = g_dest[e*TKN + r];
                    float s = g_gate[e*TKN + r];
                    *(float2*)&g_part[(size_t)p*DIMX + col] = make_float2(s*v0, s*v1);
                }
            }
        }
    }
}

// ---------------- RoPE ----------------
__global__ void rope_kernel() {
    int idx = blockIdx.x*blockDim.x + threadIdx.x;
    const int totq = TKN*NH*32;
    const int totk = TKN*NKV*32;
    float* arr; size_t base; int t, i;
    if (idx < totq) {
        arr = g_q; i = idx & 31; int rest = idx >> 5;
        int head = rest % NH; t = rest / NH;
        base = (size_t)t*DIMX + head*HD;
    } else {
        idx -= totq;
        if (idx >= totk) return;
        arr = g_k; i = idx & 31; int rest = idx >> 5;
        int head = rest % NKV; t = rest / NKV;
        base = (size_t)t*KVD + head*HD;
    }
    int pos = t % SEQ;
    float freq = expf(-(float)(2*i) * (9.210340371976184f / 64.0f));
    float ang = (float)pos * freq;
    float cs = cosf(ang), sn = sinf(ang);
    float x1 = arr[base + i], x2 = arr[base + 32 + i];
    arr[base + i]      = x1*cs - x2*sn;
    arr[base + 32 + i] = x2*cs + x1*sn;
}

// ---------------- tensor-core flash attention ----------------
// block: 256 thr (8 warps), 128 queries; k-tiles of 64. tf32 mma.
#define QSTR 68   // ≡4 mod 32: conflict-free for A-frag & K B-frag patterns
#define VSTR 72   // ≡8 mod 32: conflict-free for V B-frag pattern
#define SM_Q 0
#define SM_K (128*QSTR)
#define SM_V (SM_K + 2*64*QSTR)
#define SM_TOT ((SM_V + 2*64*VSTR)*4)

__device__ __forceinline__ void cpa16(unsigned dst, const float* src) {
    asm volatile("cp.async.cg.shared.global [%0], [%1], 16;" :: "r"(dst), "l"(src));
}

__global__ __launch_bounds__(256, 2)
void attn_mma_kernel() {
    extern __shared__ float sm[];
    int bx = blockIdx.x, h = blockIdx.y, b = blockIdx.z;
    int hk = h >> 2;
    int q0 = bx * 128;
    int tid = threadIdx.x, w = tid >> 5, lane = tid & 31;
    int g = lane >> 2, tg = lane & 3;
    unsigned smbase = (unsigned)__cvta_generic_to_shared(sm);

    // Q load (group 0, together with K0/V0)
    #pragma unroll
    for (int p = 0; p < 8; p++) {
        int id = tid + p*256;
        int r = id >> 4, c4 = (id & 15) << 2;
        cpa16(smbase + (SM_Q + r*QSTR + c4)*4,
              g_q + (size_t)(b*SEQ + q0 + r)*DIMX + h*HD + c4);
    }
    auto load_kv = [&](int kt, int bf) {
        #pragma unroll
        for (int p = 0; p < 4; p++) {
            int id = tid + p*256;
            int r = id >> 4, c4 = (id & 15) << 2;
            cpa16(smbase + (SM_K + bf*64*QSTR + r*QSTR + c4)*4,
                  g_k + (size_t)(b*SEQ + kt*64 + r)*KVD + hk*HD + c4);
            cpa16(smbase + (SM_V + bf*64*VSTR + r*VSTR + c4)*4,
                  g_v + (size_t)(b*SEQ + kt*64 + r)*KVD + hk*HD + c4);
        }
    };
    int nkt = 2*bx + 2;
    load_kv(0, 0);
    asm volatile("cp.async.commit_group;");

    int my_last = 2*bx + (w >= 4 ? 1 : 0);
    float m0 = -1.0e30f, m1 = -1.0e30f, l0 = 0.f, l1 = 0.f;
    float o[8][4] = {};
    const float SCALE = 0.18033688011112042f;  // (1/8) * log2(e)

    for (int kt = 0; kt < nkt; kt++) {
        int bf = kt & 1;
        if (kt + 1 < nkt) {
            load_kv(kt + 1, bf ^ 1);
            asm volatile("cp.async.commit_group;");
            asm volatile("cp.async.wait_group 1;");
        } else {
            asm volatile("cp.async.wait_group 0;");
        }
        __syncthreads();

        if (kt <= my_last) {
            const float* Qs = sm + SM_Q;
            const float* Ks = sm + SM_K + bf*64*QSTR;
            const float* Vs = sm + SM_V + bf*64*VSTR;
            float s[8][4] = {};
            #pragma unroll
            for (int kk = 0; kk < 8; kk++) {
                int rb = (16*w + g)*QSTR + kk*8;
                unsigned a0 = __float_as_uint(Qs[rb + tg]);
                unsigned a1 = __float_as_uint(Qs[rb + 8*QSTR + tg]);
                unsigned a2 = __float_as_uint(Qs[rb + tg + 4]);
                unsigned a3 = __float_as_uint(Qs[rb + 8*QSTR + tg + 4]);
                #pragma unroll
                for (int j = 0; j < 8; j++) {
                    unsigned b0 = __float_as_uint(Ks[(j*8 + g)*QSTR + kk*8 + tg]);
                    unsigned b1 = __float_as_uint(Ks[(j*8 + g)*QSTR + kk*8 + tg + 4]);
                    MMA_TF32(s[j], a0, a1, a2, a3, b0, b1);
                }
            }
            // scale + causal mask
            if (kt == my_last) {
                int r0 = q0 + 16*w + g, r1 = r0 + 8;
                #pragma unroll
                for (int j = 0; j < 8; j++) {
                    int cg = kt*64 + j*8 + 2*tg;
                    s[j][0] = (cg   > r0) ? -1.0e30f : s[j][0]*SCALE;
                    s[j][1] = (cg+1 > r0) ? -1.0e30f : s[j][1]*SCALE;
                    s[j][2] = (cg   > r1) ? -1.0e30f : s[j][2]*SCALE;
                    s[j][3] = (cg+1 > r1) ? -1.0e30f : s[j][3]*SCALE;
                }
            } else {
                #pragma unroll
                for (int j = 0; j < 8; j++)
                    #pragma unroll
                    for (int q = 0; q < 4; q++) s[j][q] *= SCALE;
            }
            // online softmax (rows g and g+8)
            float mx0 = -1.0e30f, mx1 = -1.0e30f;
            #pragma unroll
            for (int j = 0; j < 8; j++) {
                mx0 = fmaxf(mx0, fmaxf(s[j][0], s[j][1]));
                mx1 = fmaxf(mx1, fmaxf(s[j][2], s[j][3]));
            }
            mx0 = fmaxf(mx0, __shfl_xor_sync(0xffffffffu, mx0, 1));
            mx0 = fmaxf(mx0, __shfl_xor_sync(0xffffffffu, mx0, 2));
            mx1 = fmaxf(mx1, __shfl_xor_sync(0xffffffffu, mx1, 1));
            mx1 = fmaxf(mx1, __shfl_xor_sync(0xffffffffu, mx1, 2));
            float mn0 = fmaxf(m0, mx0), mn1 = fmaxf(m1, mx1);
            float c0 = exp2f(m0 - mn0), c1 = exp2f(m1 - mn1);
            float rs0 = 0.f, rs1 = 0.f;
            #pragma unroll
            for (int j = 0; j < 8; j++) {
                s[j][0] = exp2f(s[j][0] - mn0); s[j][1] = exp2f(s[j][1] - mn0);
                s[j][2] = exp2f(s[j][2] - mn1); s[j][3] = exp2f(s[j][3] - mn1);
                rs0 += s[j][0] + s[j][1];
                rs1 += s[j][2] + s[j][3];
            }
            rs0 += __shfl_xor_sync(0xffffffffu, rs0, 1);
            rs0 += __shfl_xor_sync(0xffffffffu, rs0, 2);
            rs1 += __shfl_xor_sync(0xffffffffu, rs1, 1);
            rs1 += __shfl_xor_sync(0xffffffffu, rs1, 2);
            l0 = l0*c0 + rs0; l1 = l1*c1 + rs1;
            m0 = mn0; m1 = mn1;
            #pragma unroll
            for (int j = 0; j < 8; j++) {
                o[j][0] *= c0; o[j][1] *= c0;
                o[j][2] *= c1; o[j][3] *= c1;
            }
            // P@V : A-frags via intra-quad shuffles of P accumulators
            int src = (lane & ~3) | (tg >> 1);
            #pragma unroll
            for (int kk = 0; kk < 8; kk++) {
                float v0 = __shfl_sync(0xffffffffu, s[kk][0], src);
                float v1 = __shfl_sync(0xffffffffu, s[kk][1], src);
                float v2 = __shfl_sync(0xffffffffu, s[kk][2], src);
                float v3 = __shfl_sync(0xffffffffu, s[kk][3], src);
                float u0 = __shfl_sync(0xffffffffu, s[kk][0], src + 2);
                float u1 = __shfl_sync(0xffffffffu, s[kk][1], src + 2);
                float u2 = __shfl_sync(0xffffffffu, s[kk][2], src + 2);
                float u3 = __shfl_sync(0xffffffffu, s[kk][3], src + 2);
                bool odd = tg & 1;
                unsigned a0 = __float_as_uint(odd ? v1 : v0);
                unsigned a1 = __float_as_uint(odd ? v3 : v2);
                unsigned a2 = __float_as_uint(odd ? u1 : u0);
                unsigned a3 = __float_as_uint(odd ? u3 : u2);
                #pragma unroll
                for (int j = 0; j < 8; j++) {
                    unsigned b0 = __float_as_uint(Vs[(kk*8 + tg)*VSTR + j*8 + g]);
                    unsigned b1 = __float_as_uint(Vs[(kk*8 + tg + 4)*VSTR + j*8 + g]);
                    MMA_TF32(o[j], a0, a1, a2, a3, b0, b1);
                }
            }
        }
        __syncthreads();
    }

    float i0 = 1.0f / l0, i1 = 1.0f / l1;
    size_t r0b = (size_t)(b*SEQ + q0 + 16*w + g    )*DIMX + h*HD;
    size_t r1b = (size_t)(b*SEQ + q0 + 16*w + g + 8)*DIMX + h*HD;
    #pragma unroll
    for (int j = 0; j < 8; j++) {
        int col = j*8 + 2*tg;
        *(float2*)&g_attn[r0b + col] = make_float2(o[j][0]*i0, o[j][1]*i0);
        *(float2*)&g_attn[r1b + col] = make_float2(o[j][2]*i1, o[j][3]*i1);
    }
}

// ---------------- router ----------------
__global__ void router_kernel(const float* __restrict__ wg) {
    int warp = (blockIdx.x*blockDim.x + threadIdx.x) >> 5;
    int lane = threadIdx.x & 31;
    if (warp >= TKN) return;
    int t = warp;
    float acc[NE] = {};
    const float* hr = g_h2 + (size_t)t*DIMX;
    for (int d = lane; d < DIMX; d += 32) {
        float hv = hr[d];
        const float* wr = wg + (size_t)d*NE;
        #pragma unroll
        for (int e = 0; e < NE; e++) acc[e] += hv * wr[e];
    }
    #pragma unroll
    for (int e = 0; e < NE; e++)
        #pragma unroll
        for (int off = 16; off > 0; off >>= 1)
            acc[e] += __shfl_xor_sync(0xffffffffu, acc[e], off);
    if (lane == 0) {
        int e0 = 0; float v0 = acc[0];
        #pragma unroll
        for (int e = 1; e < NE; e++) if (acc[e] > v0) { v0 = acc[e]; e0 = e; }
        int e1 = -1; float v1 = -3.4e38f;
        #pragma unroll
        for (int e = 0; e < NE; e++) if (e != e0 && acc[e] > v1) { v1 = acc[e]; e1 = e; }
        float ex = expf(v1 - v0);
        float den = 1.0f + ex;
        float gg0 = 1.0f/den, gg1 = ex/den;
        atomicAdd(&g_counts[e0], 1); atomicAdd(&g_counts[e1], 1);
        int p0 = atomicAdd(&g_ecnt[e0], 1);
        g_tok[e0*TKN+p0] = t; g_gate[e0*TKN+p0] = gg0; g_dest[e0*TKN+p0] = t;
        int p1 = atomicAdd(&g_ecnt[e1], 1);
        g_tok[e1*TKN+p1] = t; g_gate[e1*TKN+p1] = gg1; g_dest[e1*TKN+p1] = TKN + t;
    }
}

__global__ void combine_kernel(float* __restrict__ out) {
    int i = blockIdx.x*256 + threadIdx.x;
    out[i] = g_x1[i] + g_part[i] + g_part[TKN*DIMX + i];
}

__global__ void lb_kernel(float* __restrict__ out, int out_size) {
    if (threadIdx.x == 0) {
        float tot = 0.f;
        for (int e = 0; e < NE; e++) tot += (float)g_counts[e];
        float loss = 0.f;
        for (int e = 0; e < NE; e++) {
            float cn = (float)g_counts[e]/tot - 1.0f/NE;
            loss += cn*cn;
        }
        out[out_size - 1] = loss / NE;
    }
}

// ---------------- launch ----------------
extern "C" void kernel_launch(void* const* d_in, const int* in_sizes, int n_in,
                              void* d_out, int out_size) {
    const float* x    = (const float*)d_in[0];
    const float* wq   = (const float*)d_in[1];
    const float* wk   = (const float*)d_in[2];
    const float* wv   = (const float*)d_in[3];
    const float* wo   = (const float*)d_in[4];
    const float* wg   = (const float*)d_in[5];
    const float* w1   = (const float*)d_in[6];
    const float* w2   = (const float*)d_in[7];
    const float* ln1g = (const float*)d_in[8];
    const float* ln1b = (const float*)d_in[9];
    const float* ln2g = (const float*)d_in[10];
    const float* ln2b = (const float*)d_in[11];
    float* out = (float*)d_out;

    float *p_h1, *p_attn, *p_x1, *p_h2;
    cudaGetSymbolAddress((void**)&p_h1,  g_h1);
    cudaGetSymbolAddress((void**)&p_attn,g_attn);
    cudaGetSymbolAddress((void**)&p_x1,  g_x1);
    cudaGetSymbolAddress((void**)&p_h2,  g_h2);

    static int smem_set = 0;
    if (!smem_set) {
        cudaFuncSetAttribute(attn_mma_kernel,
                             cudaFuncAttributeMaxDynamicSharedMemorySize, SM_TOT);
        smem_set = 1;
    }

    zero_kernel<<<1, 32>>>();
    ln_kernel<<<TKN, 256>>>(x, ln1g, ln1b, p_h1);

    // fused QKV projection (N = 1024 + 256 + 256)
    mma_gemm<4><<<dim3((DIMX+2*KVD)/BN, TKN/BM, 1), 256>>>(
        p_h1, wq, nullptr, nullptr, wk, wv, TKN, DIMX, DIMX);

    rope_kernel<<<(TKN*(NH+NKV)*32)/256, 256>>>();
    attn_mma_kernel<<<dim3(SEQ/128, NH, BATCH), 256, SM_TOT>>>();

    mma_gemm<1><<<dim3(DIMX/BN, TKN/BM, 1), 256>>>(
        p_attn, wo, p_x1, x, nullptr, nullptr, TKN, DIMX, DIMX);
    ln_kernel<<<TKN, 256>>>(p_x1, ln2g, ln2b, p_h2);

    router_kernel<<<TKN/8, 256>>>(wg);

    mma_gemm<2><<<dim3(FFX/BN,  TKN/BM, NE), 256>>>(
        nullptr, w1, nullptr, nullptr, nullptr, nullptr, TKN, FFX, DIMX);
    mma_gemm<3><<<dim3(DIMX/BN, TKN/BM, NE), 256>>>(
        nullptr, w2, nullptr, nullptr, nullptr, nullptr, TKN, DIMX, FFX);

    combine_kernel<<<(TKN*DIMX)/256, 256>>>(out);
    lb_kernel<<<1, 32>>>(out, out_size);
}

// round 4
// speedup vs baseline: 6.2436x; 1.6195x over previous
#include <cuda_runtime.h>
#include <cuda_fp16.h>
#include <math.h>

#define TKN 2048
#define BATCH 2
#define SEQ 1024
#define DIMX 1024
#define NH 16
#define NKV 4
#define HD 64
#define KVD (NKV*HD)   // 256
#define NE 8
#define FFX 4096

// ---------------- scratch ----------------
__device__ float g_q [TKN*DIMX];
__device__ float g_k [TKN*KVD];
__device__ float g_v [TKN*KVD];
__device__ float g_x1[TKN*DIMX];
__device__ float g_part[2*TKN*DIMX];
__device__ __half g_h1h [TKN*DIMX];
__device__ __half g_attnh[TKN*DIMX];
__device__ __half g_h2h [TKN*DIMX];
__device__ __half g_hidh[(size_t)NE*TKN*FFX];
__device__ __half g_wq16[DIMX*DIMX];
__device__ __half g_wk16[DIMX*KVD];
__device__ __half g_wv16[DIMX*KVD];
__device__ __half g_wo16[DIMX*DIMX];
__device__ __half g_w116[(size_t)NE*DIMX*FFX];
__device__ __half g_w216[(size_t)NE*FFX*DIMX];
__device__ int   g_tok [NE*TKN];
__device__ float g_gate[NE*TKN];
__device__ int   g_dest[NE*TKN];
__device__ int   g_ecnt[NE];
__device__ int   g_counts[NE];

__global__ void zero_kernel() {
    int i = threadIdx.x;
    if (i < NE) { g_ecnt[i] = 0; g_counts[i] = 0; }
}

// ---------------- fp32 -> fp16 convert (per 8 elements) ----------------
__global__ void cvt_kernel(const float* __restrict__ s, __half* __restrict__ d, int n8) {
    int i = blockIdx.x*256 + threadIdx.x;
    if (i >= n8) return;
    float4 a = ((const float4*)s)[2*i];
    float4 b = ((const float4*)s)[2*i + 1];
    __half2 h0 = __floats2half2_rn(a.x, a.y);
    __half2 h1 = __floats2half2_rn(a.z, a.w);
    __half2 h2 = __floats2half2_rn(b.x, b.y);
    __half2 h3 = __floats2half2_rn(b.z, b.w);
    uint4 u;
    u.x = ((unsigned)__half_as_ushort(__high2half(h0)) << 16) | __half_as_ushort(__low2half(h0));
    u.y = ((unsigned)__half_as_ushort(__high2half(h1)) << 16) | __half_as_ushort(__low2half(h1));
    u.z = ((unsigned)__half_as_ushort(__high2half(h2)) << 16) | __half_as_ushort(__low2half(h2));
    u.w = ((unsigned)__half_as_ushort(__high2half(h3)) << 16) | __half_as_ushort(__low2half(h3));
    ((uint4*)d)[i] = u;
}

// ---------------- layernorm -> fp16 ----------------
__global__ void ln_kernel(const float* __restrict__ x, const float* __restrict__ g,
                          const float* __restrict__ b, __half* __restrict__ out) {
    int row = blockIdx.x;
    int tid = threadIdx.x;
    const float* xr = x + (size_t)row * DIMX;
    float v[4]; float s = 0.f;
    #pragma unroll
    for (int j = 0; j < 4; j++) { v[j] = xr[tid + 256*j]; s += v[j]; }
    __shared__ float red[8];
    #pragma unroll
    for (int o = 16; o > 0; o >>= 1) s += __shfl_xor_sync(0xffffffffu, s, o);
    if ((tid & 31) == 0) red[tid >> 5] = s;
    __syncthreads();
    float tot = red[0]+red[1]+red[2]+red[3]+red[4]+red[5]+red[6]+red[7];
    float mu = tot / DIMX;
    float sq = 0.f;
    #pragma unroll
    for (int j = 0; j < 4; j++) { float d = v[j]-mu; sq += d*d; }
    #pragma unroll
    for (int o = 16; o > 0; o >>= 1) sq += __shfl_xor_sync(0xffffffffu, sq, o);
    __syncthreads();
    if ((tid & 31) == 0) red[tid >> 5] = sq;
    __syncthreads();
    float vtot = red[0]+red[1]+red[2]+red[3]+red[4]+red[5]+red[6]+red[7];
    float rstd = rsqrtf(vtot / DIMX + 1e-5f);
    #pragma unroll
    for (int j = 0; j < 4; j++) {
        int d = tid + 256*j;
        out[(size_t)row*DIMX + d] = __float2half_rn((v[j]-mu)*rstd*g[d] + b[d]);
    }
}

// ---------------- fp16 tensor-core GEMM (m16n8k16, ldmatrix, 3-stage) ----------------
// MODE 1: C=A@B+resid (fp32 out)  MODE 2: MoE up (gather, GELU, fp16 out)
// MODE 3: MoE down (scatter*gate, fp32)  MODE 4: fused QKV (fp32 q/k/v out)
#define ASTG (128*40)     // halves per A stage
#define BSTG (32*136)     // halves per B stage
#define BBASE (3*ASTG)
#define SMEMB ((BBASE + 3*BSTG)*2)

#define LDSM4(R, addr) \
    asm volatile("ldmatrix.sync.aligned.m8n8.x4.shared.b16 {%0,%1,%2,%3}, [%4];" \
        : "=r"(R[0]), "=r"(R[1]), "=r"(R[2]), "=r"(R[3]) : "r"(addr))
#define LDSM4T(R, addr) \
    asm volatile("ldmatrix.sync.aligned.m8n8.x4.trans.shared.b16 {%0,%1,%2,%3}, [%4];" \
        : "=r"(R[0]), "=r"(R[1]), "=r"(R[2]), "=r"(R[3]) : "r"(addr))
#define MMA_F16(C4, A4, B0, B1) \
    asm volatile("mma.sync.aligned.m16n8k16.row.col.f32.f16.f16.f32 " \
        "{%0,%1,%2,%3},{%4,%5,%6,%7},{%8,%9},{%0,%1,%2,%3};" \
        : "+f"(C4[0]), "+f"(C4[1]), "+f"(C4[2]), "+f"(C4[3]) \
        : "r"(A4[0]), "r"(A4[1]), "r"(A4[2]), "r"(A4[3]), "r"(B0), "r"(B1))

template<int MODE>
__global__ __launch_bounds__(256, 2)
void hgemm(const __half* __restrict__ A, const __half* __restrict__ Bm,
           float* __restrict__ C, const float* __restrict__ resid,
           int M, int N, int K) {
    extern __shared__ __half smh[];
    int e = blockIdx.z;
    int ldB = N, ldC = N;
    int n0 = blockIdx.x * 128, cbase = n0;
    __half* C16 = nullptr;
    if (MODE == 2) { M = g_ecnt[e]; A = g_h2h; Bm = g_w116 + (size_t)e*DIMX*FFX; C16 = g_hidh + (size_t)e*TKN*FFX; }
    if (MODE == 3) { M = g_ecnt[e]; A = g_hidh + (size_t)e*TKN*FFX; Bm = g_w216 + (size_t)e*FFX*DIMX; ldC = DIMX; }
    if (MODE == 4) {
        if (n0 < DIMX)            { Bm = g_wq16; ldB = DIMX; C = g_q; ldC = DIMX; cbase = n0; }
        else if (n0 < DIMX + KVD) { Bm = g_wk16; ldB = KVD;  C = g_k; ldC = KVD;  cbase = n0 - DIMX; }
        else                      { Bm = g_wv16; ldB = KVD;  C = g_v; ldC = KVD;  cbase = n0 - DIMX - KVD; }
    }
    int m0 = blockIdx.y * 128;
    if (m0 >= M) return;
    int tid = threadIdx.x;
    int warp = tid >> 5, lane = tid & 31;
    int wm = warp >> 2, wn = warp & 3;   // warp tile 64x32
    int g = lane >> 2, tg = lane & 3;

    // staging slots
    const __half* aSrc[2]; int aSz[2]; unsigned aOff[2];
    #pragma unroll
    for (int p = 0; p < 2; p++) {
        int id = tid + p*256;
        int r = id >> 2, c8 = (id & 3) << 3;
        int rg = m0 + r;
        bool valid = rg < M;
        const __half* ptr;
        if (MODE == 2) {
            int t = valid ? g_tok[e*TKN + rg] : 0;
            ptr = A + (size_t)t*K + c8;
        } else {
            ptr = A + (size_t)(valid ? rg : 0)*K + c8;
        }
        aSrc[p] = ptr; aSz[p] = valid ? 16 : 0;
        aOff[p] = (r*40 + c8)*2;
    }
    const __half* bSrc[2]; unsigned bOff[2];
    #pragma unroll
    for (int p = 0; p < 2; p++) {
        int id = tid + p*256;
        int r = id >> 4, c8 = (id & 15) << 3;
        bSrc[p] = Bm + (size_t)r*ldB + cbase + c8;
        bOff[p] = (BBASE + r*136 + c8)*2;
    }
    unsigned smb = (unsigned)__cvta_generic_to_shared(smh);

    auto load_stage = [&](int s, int kt) {
        int k0 = kt*32;
        #pragma unroll
        for (int p = 0; p < 2; p++)
            asm volatile("cp.async.cg.shared.global [%0], [%1], 16, %2;"
                :: "r"(smb + s*(ASTG*2) + aOff[p]), "l"(aSrc[p] + k0), "r"(aSz[p]));
        #pragma unroll
        for (int p = 0; p < 2; p++)
            asm volatile("cp.async.cg.shared.global [%0], [%1], 16;"
                :: "r"(smb + s*(BSTG*2) + bOff[p]), "l"(bSrc[p] + (size_t)k0*ldB));
        asm volatile("cp.async.commit_group;");
    };

    unsigned aBase = smb + ((wm*64 + ((lane>>3)&1)*8 + (lane&7))*40 + (lane>>4)*8)*2;
    unsigned bBase = smb + BBASE*2 + ((((lane>>3)&1)*8 + (lane&7))*136 + wn*32 + (lane>>4)*8)*2;

    float c[4][4][4] = {};
    int nk = K / 32;
    load_stage(0, 0);
    load_stage(1, 1);
    for (int kt = 0; kt < nk; kt++) {
        int s = kt % 3;
        if (kt < nk - 1) asm volatile("cp.async.wait_group 1;");
        else             asm volatile("cp.async.wait_group 0;");
        __syncthreads();
        unsigned aS = aBase + s*(ASTG*2);
        unsigned bS = bBase + s*(BSTG*2);
        #pragma unroll
        for (int ks = 0; ks < 2; ks++) {
            unsigned af[4][4], bq[2][4];
            #pragma unroll
            for (int i = 0; i < 4; i++)
                LDSM4(af[i], aS + (i*16*40 + ks*16)*2);
            #pragma unroll
            for (int jp = 0; jp < 2; jp++)
                LDSM4T(bq[jp], bS + (ks*16*136 + jp*16)*2);
            #pragma unroll
            for (int i = 0; i < 4; i++)
                #pragma unroll
                for (int j = 0; j < 4; j++)
                    MMA_F16(c[i][j], af[i], bq[j>>1][(j&1)*2], bq[j>>1][(j&1)*2+1]);
        }
        if (kt + 2 < nk) load_stage((kt+2) % 3, kt+2);
    }

    // epilogue
    #pragma unroll
    for (int i = 0; i < 4; i++) {
        #pragma unroll
        for (int half = 0; half < 2; half++) {
            int r = m0 + wm*64 + i*16 + g + half*8;
            if ((MODE == 2 || MODE == 3) && r >= M) continue;
            #pragma unroll
            for (int j = 0; j < 4; j++) {
                float v0 = c[i][j][half*2 + 0];
                float v1 = c[i][j][half*2 + 1];
                int col = cbase + wn*32 + j*8 + 2*tg;
                if (MODE == 4) {
                    *(float2*)&C[(size_t)r*ldC + col] = make_float2(v0, v1);
                } else if (MODE == 1) {
                    float2 rr = *(const float2*)&resid[(size_t)r*ldC + col];
                    *(float2*)&C[(size_t)r*ldC + col] = make_float2(v0+rr.x, v1+rr.y);
                } else if (MODE == 2) {
                    float o0 = 0.5f*v0*(1.0f + erff(v0*0.70710678118654752f));
                    float o1 = 0.5f*v1*(1.0f + erff(v1*0.70710678118654752f));
                    *(__half2*)&C16[(size_t)r*ldC + col] = __floats2half2_rn(o0, o1);
                } else {
                    int p = g_dest[e*TKN + r];
                    float s = g_gate[e*TKN + r];
                    *(float2*)&g_part[(size_t)p*DIMX + col] = make_float2(s*v0, s*v1);
                }
            }
        }
    }
}

// ---------------- RoPE (fp32, in place) ----------------
__global__ void rope_kernel() {
    int idx = blockIdx.x*blockDim.x + threadIdx.x;
    const int totq = TKN*NH*32;
    const int totk = TKN*NKV*32;
    float* arr; size_t base; int t, i;
    if (idx < totq) {
        arr = g_q; i = idx & 31; int rest = idx >> 5;
        int head = rest % NH; t = rest / NH;
        base = (size_t)t*DIMX + head*HD;
    } else {
        idx -= totq;
        if (idx >= totk) return;
        arr = g_k; i = idx & 31; int rest = idx >> 5;
        int head = rest % NKV; t = rest / NKV;
        base = (size_t)t*KVD + head*HD;
    }
    int pos = t % SEQ;
    float freq = expf(-(float)(2*i) * (9.210340371976184f / 64.0f));
    float ang = (float)pos * freq;
    float cs = cosf(ang), sn = sinf(ang);
    float x1 = arr[base + i], x2 = arr[base + 32 + i];
    arr[base + i]      = x1*cs - x2*sn;
    arr[base + 32 + i] = x2*cs + x1*sn;
}

// ---------------- tf32 tensor-core flash attention (unchanged core) ----------------
#define MMA_TF32(C4, A0,A1,A2,A3, B0,B1) \
    asm volatile("mma.sync.aligned.m16n8k8.row.col.f32.tf32.tf32.f32 " \
        "{%0,%1,%2,%3},{%4,%5,%6,%7},{%8,%9},{%0,%1,%2,%3};" \
        : "+f"(C4[0]), "+f"(C4[1]), "+f"(C4[2]), "+f"(C4[3]) \
        : "r"(A0), "r"(A1), "r"(A2), "r"(A3), "r"(B0), "r"(B1))

#define QSTR 68
#define VSTR 72
#define SM_Q 0
#define SM_K (128*QSTR)
#define SM_V (SM_K + 2*64*QSTR)
#define SM_TOT ((SM_V + 2*64*VSTR)*4)

__device__ __forceinline__ void cpa16(unsigned dst, const float* src) {
    asm volatile("cp.async.cg.shared.global [%0], [%1], 16;" :: "r"(dst), "l"(src));
}

__global__ __launch_bounds__(256, 2)
void attn_mma_kernel() {
    extern __shared__ float sm[];
    int bx = blockIdx.x, h = blockIdx.y, b = blockIdx.z;
    int hk = h >> 2;
    int q0 = bx * 128;
    int tid = threadIdx.x, w = tid >> 5, lane = tid & 31;
    int g = lane >> 2, tg = lane & 3;
    unsigned smbase = (unsigned)__cvta_generic_to_shared(sm);

    #pragma unroll
    for (int p = 0; p < 8; p++) {
        int id = tid + p*256;
        int r = id >> 4, c4 = (id & 15) << 2;
        cpa16(smbase + (SM_Q + r*QSTR + c4)*4,
              g_q + (size_t)(b*SEQ + q0 + r)*DIMX + h*HD + c4);
    }
    auto load_kv = [&](int kt, int bf) {
        #pragma unroll
        for (int p = 0; p < 4; p++) {
            int id = tid + p*256;
            int r = id >> 4, c4 = (id & 15) << 2;
            cpa16(smbase + (SM_K + bf*64*QSTR + r*QSTR + c4)*4,
                  g_k + (size_t)(b*SEQ + kt*64 + r)*KVD + hk*HD + c4);
            cpa16(smbase + (SM_V + bf*64*VSTR + r*VSTR + c4)*4,
                  g_v + (size_t)(b*SEQ + kt*64 + r)*KVD + hk*HD + c4);
        }
    };
    int nkt = 2*bx + 2;
    load_kv(0, 0);
    asm volatile("cp.async.commit_group;");

    int my_last = 2*bx + (w >= 4 ? 1 : 0);
    float m0 = -1.0e30f, m1 = -1.0e30f, l0 = 0.f, l1 = 0.f;
    float o[8][4] = {};
    const float SCALE = 0.18033688011112042f;  // (1/8)*log2(e)

    for (int kt = 0; kt < nkt; kt++) {
        int bf = kt & 1;
        if (kt + 1 < nkt) {
            load_kv(kt + 1, bf ^ 1);
            asm volatile("cp.async.commit_group;");
            asm volatile("cp.async.wait_group 1;");
        } else {
            asm volatile("cp.async.wait_group 0;");
        }
        __syncthreads();

        if (kt <= my_last) {
            const float* Qs = sm + SM_Q;
            const float* Ks = sm + SM_K + bf*64*QSTR;
            const float* Vs = sm + SM_V + bf*64*VSTR;
            float s[8][4] = {};
            #pragma unroll
            for (int kk = 0; kk < 8; kk++) {
                int rb = (16*w + g)*QSTR + kk*8;
                unsigned a0 = __float_as_uint(Qs[rb + tg]);
                unsigned a1 = __float_as_uint(Qs[rb + 8*QSTR + tg]);
                unsigned a2 = __float_as_uint(Qs[rb + tg + 4]);
                unsigned a3 = __float_as_uint(Qs[rb + 8*QSTR + tg + 4]);
                #pragma unroll
                for (int j = 0; j < 8; j++) {
                    unsigned b0 = __float_as_uint(Ks[(j*8 + g)*QSTR + kk*8 + tg]);
                    unsigned b1 = __float_as_uint(Ks[(j*8 + g)*QSTR + kk*8 + tg + 4]);
                    MMA_TF32(s[j], a0, a1, a2, a3, b0, b1);
                }
            }
            if (kt == my_last) {
                int r0 = q0 + 16*w + g, r1 = r0 + 8;
                #pragma unroll
                for (int j = 0; j < 8; j++) {
                    int cg = kt*64 + j*8 + 2*tg;
                    s[j][0] = (cg   > r0) ? -1.0e30f : s[j][0]*SCALE;
                    s[j][1] = (cg+1 > r0) ? -1.0e30f : s[j][1]*SCALE;
                    s[j][2] = (cg   > r1) ? -1.0e30f : s[j][2]*SCALE;
                    s[j][3] = (cg+1 > r1) ? -1.0e30f : s[j][3]*SCALE;
                }
            } else {
                #pragma unroll
                for (int j = 0; j < 8; j++)
                    #pragma unroll
                    for (int q = 0; q < 4; q++) s[j][q] *= SCALE;
            }
            float mx0 = -1.0e30f, mx1 = -1.0e30f;
            #pragma unroll
            for (int j = 0; j < 8; j++) {
                mx0 = fmaxf(mx0, fmaxf(s[j][0], s[j][1]));
                mx1 = fmaxf(mx1, fmaxf(s[j][2], s[j][3]));
            }
            mx0 = fmaxf(mx0, __shfl_xor_sync(0xffffffffu, mx0, 1));
            mx0 = fmaxf(mx0, __shfl_xor_sync(0xffffffffu, mx0, 2));
            mx1 = fmaxf(mx1, __shfl_xor_sync(0xffffffffu, mx1, 1));
            mx1 = fmaxf(mx1, __shfl_xor_sync(0xffffffffu, mx1, 2));
            float mn0 = fmaxf(m0, mx0), mn1 = fmaxf(m1, mx1);
            float c0 = exp2f(m0 - mn0), c1 = exp2f(m1 - mn1);
            float rs0 = 0.f, rs1 = 0.f;
            #pragma unroll
            for (int j = 0; j < 8; j++) {
                s[j][0] = exp2f(s[j][0] - mn0); s[j][1] = exp2f(s[j][1] - mn0);
                s[j][2] = exp2f(s[j][2] - mn1); s[j][3] = exp2f(s[j][3] - mn1);
                rs0 += s[j][0] + s[j][1];
                rs1 += s[j][2] + s[j][3];
            }
            rs0 += __shfl_xor_sync(0xffffffffu, rs0, 1);
            rs0 += __shfl_xor_sync(0xffffffffu, rs0, 2);
            rs1 += __shfl_xor_sync(0xffffffffu, rs1, 1);
            rs1 += __shfl_xor_sync(0xffffffffu, rs1, 2);
            l0 = l0*c0 + rs0; l1 = l1*c1 + rs1;
            m0 = mn0; m1 = mn1;
            #pragma unroll
            for (int j = 0; j < 8; j++) {
                o[j][0] *= c0; o[j][1] *= c0;
                o[j][2] *= c1; o[j][3] *= c1;
            }
            int src = (lane & ~3) | (tg >> 1);
            #pragma unroll
            for (int kk = 0; kk < 8; kk++) {
                float v0 = __shfl_sync(0xffffffffu, s[kk][0], src);
                float v1 = __shfl_sync(0xffffffffu, s[kk][1], src);
                float v2 = __shfl_sync(0xffffffffu, s[kk][2], src);
                float v3 = __shfl_sync(0xffffffffu, s[kk][3], src);
                float u0 = __shfl_sync(0xffffffffu, s[kk][0], src + 2);
                float u1 = __shfl_sync(0xffffffffu, s[kk][1], src + 2);
                float u2 = __shfl_sync(0xffffffffu, s[kk][2], src + 2);
                float u3 = __shfl_sync(0xffffffffu, s[kk][3], src + 2);
                bool odd = tg & 1;
                unsigned a0 = __float_as_uint(odd ? v1 : v0);
                unsigned a1 = __float_as_uint(odd ? v3 : v2);
                unsigned a2 = __float_as_uint(odd ? u1 : u0);
                unsigned a3 = __float_as_uint(odd ? u3 : u2);
                #pragma unroll
                for (int j = 0; j < 8; j++) {
                    unsigned b0 = __float_as_uint(Vs[(kk*8 + tg)*VSTR + j*8 + g]);
                    unsigned b1 = __float_as_uint(Vs[(kk*8 + tg + 4)*VSTR + j*8 + g]);
                    MMA_TF32(o[j], a0, a1, a2, a3, b0, b1);
                }
            }
        }
        __syncthreads();
    }

    float i0 = 1.0f / l0, i1 = 1.0f / l1;
    size_t r0b = (size_t)(b*SEQ + q0 + 16*w + g    )*DIMX + h*HD;
    size_t r1b = (size_t)(b*SEQ + q0 + 16*w + g + 8)*DIMX + h*HD;
    #pragma unroll
    for (int j = 0; j < 8; j++) {
        int col = j*8 + 2*tg;
        *(__half2*)&g_attnh[r0b + col] = __floats2half2_rn(o[j][0]*i0, o[j][1]*i0);
        *(__half2*)&g_attnh[r1b + col] = __floats2half2_rn(o[j][2]*i1, o[j][3]*i1);
    }
}

// ---------------- router (fp16 h2 x fp32 wg) ----------------
__global__ void router_kernel(const float* __restrict__ wg) {
    int warp = (blockIdx.x*blockDim.x + threadIdx.x) >> 5;
    int lane = threadIdx.x & 31;
    if (warp >= TKN) return;
    int t = warp;
    float acc[NE] = {};
    const __half* hr = g_h2h + (size_t)t*DIMX;
    for (int d = lane; d < DIMX; d += 32) {
        float hv = __half2float(hr[d]);
        const float* wr = wg + (size_t)d*NE;
        #pragma unroll
        for (int e = 0; e < NE; e++) acc[e] += hv * wr[e];
    }
    #pragma unroll
    for (int e = 0; e < NE; e++)
        #pragma unroll
        for (int off = 16; off > 0; off >>= 1)
            acc[e] += __shfl_xor_sync(0xffffffffu, acc[e], off);
    if (lane == 0) {
        int e0 = 0; float v0 = acc[0];
        #pragma unroll
        for (int e = 1; e < NE; e++) if (acc[e] > v0) { v0 = acc[e]; e0 = e; }
        int e1 = -1; float v1 = -3.4e38f;
        #pragma unroll
        for (int e = 0; e < NE; e++) if (e != e0 && acc[e] > v1) { v1 = acc[e]; e1 = e; }
        float ex = expf(v1 - v0);
        float den = 1.0f + ex;
        float gg0 = 1.0f/den, gg1 = ex/den;
        atomicAdd(&g_counts[e0], 1); atomicAdd(&g_counts[e1], 1);
        int p0 = atomicAdd(&g_ecnt[e0], 1);
        g_tok[e0*TKN+p0] = t; g_gate[e0*TKN+p0] = gg0; g_dest[e0*TKN+p0] = t;
        int p1 = atomicAdd(&g_ecnt[e1], 1);
        g_tok[e1*TKN+p1] = t; g_gate[e1*TKN+p1] = gg1; g_dest[e1*TKN+p1] = TKN + t;
    }
}

__global__ void combine_kernel(float* __restrict__ out) {
    int i = blockIdx.x*256 + threadIdx.x;
    out[i] = g_x1[i] + g_part[i] + g_part[TKN*DIMX + i];
}

__global__ void lb_kernel(float* __restrict__ out, int out_size) {
    if (threadIdx.x == 0) {
        float tot = 0.f;
        for (int e = 0; e < NE; e++) tot += (float)g_counts[e];
        float loss = 0.f;
        for (int e = 0; e < NE; e++) {
            float cn = (float)g_counts[e]/tot - 1.0f/NE;
            loss += cn*cn;
        }
        out[out_size - 1] = loss / NE;
    }
}

// ---------------- launch ----------------
extern "C" void kernel_launch(void* const* d_in, const int* in_sizes, int n_in,
                              void* d_out, int out_size) {
    const float* x    = (const float*)d_in[0];
    const float* wq   = (const float*)d_in[1];
    const float* wk   = (const float*)d_in[2];
    const float* wv   = (const float*)d_in[3];
    const float* wo   = (const float*)d_in[4];
    const float* wg   = (const float*)d_in[5];
    const float* w1   = (const float*)d_in[6];
    const float* w2   = (const float*)d_in[7];
    const float* ln1g = (const float*)d_in[8];
    const float* ln1b = (const float*)d_in[9];
    const float* ln2g = (const float*)d_in[10];
    const float* ln2b = (const float*)d_in[11];
    float* out = (float*)d_out;

    float *p_x1;
    __half *p_h1h, *p_attnh, *p_h2h;
    __half *p_wq16, *p_wk16, *p_wv16, *p_wo16, *p_w116, *p_w216;
    cudaGetSymbolAddress((void**)&p_x1,   g_x1);
    cudaGetSymbolAddress((void**)&p_h1h,  g_h1h);
    cudaGetSymbolAddress((void**)&p_attnh,g_attnh);
    cudaGetSymbolAddress((void**)&p_h2h,  g_h2h);
    cudaGetSymbolAddress((void**)&p_wq16, g_wq16);
    cudaGetSymbolAddress((void**)&p_wk16, g_wk16);
    cudaGetSymbolAddress((void**)&p_wv16, g_wv16);
    cudaGetSymbolAddress((void**)&p_wo16, g_wo16);
    cudaGetSymbolAddress((void**)&p_w116, g_w116);
    cudaGetSymbolAddress((void**)&p_w216, g_w216);

    static int attr_set = 0;
    if (!attr_set) {
        cudaFuncSetAttribute(attn_mma_kernel,
                             cudaFuncAttributeMaxDynamicSharedMemorySize, SM_TOT);
        cudaFuncSetAttribute(hgemm<1>, cudaFuncAttributeMaxDynamicSharedMemorySize, SMEMB);
        cudaFuncSetAttribute(hgemm<2>, cudaFuncAttributeMaxDynamicSharedMemorySize, SMEMB);
        cudaFuncSetAttribute(hgemm<3>, cudaFuncAttributeMaxDynamicSharedMemorySize, SMEMB);
        cudaFuncSetAttribute(hgemm<4>, cudaFuncAttributeMaxDynamicSharedMemorySize, SMEMB);
        attr_set = 1;
    }

    zero_kernel<<<1, 32>>>();
    // weight conversions
    cvt_kernel<<<(DIMX*DIMX/8 + 255)/256, 256>>>(wq, p_wq16, DIMX*DIMX/8);
    cvt_kernel<<<(DIMX*KVD/8 + 255)/256, 256>>>(wk, p_wk16, DIMX*KVD/8);
    cvt_kernel<<<(DIMX*KVD/8 + 255)/256, 256>>>(wv, p_wv16, DIMX*KVD/8);
    cvt_kernel<<<(DIMX*DIMX/8 + 255)/256, 256>>>(wo, p_wo16, DIMX*DIMX/8);
    cvt_kernel<<<(NE*DIMX*FFX/8 + 255)/256, 256>>>(w1, p_w116, NE*DIMX*FFX/8);
    cvt_kernel<<<(NE*FFX*DIMX/8 + 255)/256, 256>>>(w2, p_w216, NE*FFX*DIMX/8);

    ln_kernel<<<TKN, 256>>>(x, ln1g, ln1b, p_h1h);

    hgemm<4><<<dim3((DIMX+2*KVD)/128, TKN/128, 1), 256, SMEMB>>>(
        p_h1h, nullptr, nullptr, nullptr, TKN, DIMX, DIMX);

    rope_kernel<<<(TKN*(NH+NKV)*32)/256, 256>>>();
    attn_mma_kernel<<<dim3(SEQ/128, NH, BATCH), 256, SM_TOT>>>();

    hgemm<1><<<dim3(DIMX/128, TKN/128, 1), 256, SMEMB>>>(
        p_attnh, p_wo16, p_x1, x, TKN, DIMX, DIMX);
    ln_kernel<<<TKN, 256>>>(p_x1, ln2g, ln2b, p_h2h);

    router_kernel<<<TKN/8, 256>>>(wg);

    hgemm<2><<<dim3(FFX/128,  TKN/128, NE), 256, SMEMB>>>(
        nullptr, nullptr, nullptr, nullptr, TKN, FFX, DIMX);
    hgemm<3><<<dim3(DIMX/128, TKN/128, NE), 256, SMEMB>>>(
        nullptr, nullptr, nullptr, nullptr, TKN, DIMX, FFX);

    combine_kernel<<<(TKN*DIMX)/256, 256>>>(out);
    lb_kernel<<<1, 32>>>(out, out_size);
}